// round 14
// baseline (speedup 1.0000x reference)
#include <cuda_runtime.h>
#include <cuda_fp16.h>
#include <cstdint>
#include <math.h>

// Problem constants
#define TT    4
#define BB    64
#define CC    384
#define NN    196
#define NP    208             // padded N (mult of 16; rows 196..207 zeroed)
#define NH    104             // N half per CTA
#define NHEAD 8
#define DHD   48
#define CN    (CC*NN)          // 75264
#define BCN   (BB*CC*NN)       // 4816896
#define TBCN  (TT*BCN)         // 19267584
#define BHN   (BB*NHEAD*NN)    // 100352
#define ZTOT  (TT*BB)          // 256

// GEMM SMEM: stage = Ahi(128x40h) Alo(128x40h) B(104x40h); 3 stages; 2 CTA/SM.
#define S_ALO   10240
#define S_B     20480
#define S_STG   28800
#define SMEM_G  (3*S_STG)      // 86400 (x2 CTAs = 172.8KB <= 228KB)

#define REPAIR_QK  4e-3f
#define REPAIR_OUT 2.5e-4f
#define FIXCAP     (1<<21)

// Scratch (allocation-free: __device__ globals)
__device__ float   g_pre[2u*TBCN];
__device__ float   g_xt [(size_t)ZTOT*NP*CC];   // fp32 x, [z][n][c] (repair)
__device__ __half  g_xhi[(size_t)ZTOT*NP*CC];   // fp16(x), [z][n][c]
__device__ __half  g_yt [(size_t)ZTOT*NP*CC];   // {0,1}
__device__ __half  g_whi[3*CC*CC];              // [sel][m][k] sel:0=q,1=k,2=p
__device__ __half  g_wlo[3*CC*CC];
__device__ unsigned char g_qs[TBCN];
__device__ unsigned char g_ks[TBCN];
__device__ unsigned char g_attn[(size_t)TT*BHN];
__device__ float   g_scale[3*CC];
__device__ unsigned int g_nfix;
__device__ unsigned int g_nfix2;
__device__ int     g_fix [FIXCAP];
__device__ int     g_fix2[FIXCAP];

// ---------------------------------------------------------------------------
__device__ __forceinline__ uint32_t smem_u32(const void* p) {
    uint32_t a;
    asm("{ .reg .u64 t; cvta.to.shared.u64 t, %1; cvt.u32.u64 %0, t; }"
        : "=r"(a) : "l"(p));
    return a;
}
__device__ __forceinline__ void cp16(uint32_t s, const void* g) {
    asm volatile("cp.async.cg.shared.global [%0], [%1], 16;"
                 :: "r"(s), "l"(g) : "memory");
}
#define CP_COMMIT() asm volatile("cp.async.commit_group;" ::: "memory")
#define CP_WAIT(n)  asm volatile("cp.async.wait_group %0;" :: "n"(n) : "memory")

__device__ __forceinline__ void mma_f16(float* d, const uint32_t* a,
                                        uint32_t b0, uint32_t b1) {
    asm volatile(
        "mma.sync.aligned.m16n8k16.row.col.f32.f16.f16.f32 "
        "{%0,%1,%2,%3}, {%4,%5,%6,%7}, {%8,%9}, {%0,%1,%2,%3};"
        : "+f"(d[0]), "+f"(d[1]), "+f"(d[2]), "+f"(d[3])
        : "r"(a[0]), "r"(a[1]), "r"(a[2]), "r"(a[3]), "r"(b0), "r"(b1));
}

// ---------------------------------------------------------------------------
__global__ void reset_counters()
{
    if (threadIdx.x == 0) { g_nfix = 0; g_nfix2 = 0; }
}

// ---------------------------------------------------------------------------
__global__ void bn_precompute(const float* __restrict__ qg, const float* __restrict__ qv,
                              const float* __restrict__ kg, const float* __restrict__ kv,
                              const float* __restrict__ pg, const float* __restrict__ pv)
{
    int c = threadIdx.x;
    if (c < CC) {
        g_scale[c]        = qg[c] / sqrtf(qv[c] + 1e-5f);
        g_scale[CC + c]   = kg[c] / sqrtf(kv[c] + 1e-5f);
        g_scale[2*CC + c] = pg[c] / sqrtf(pv[c] + 1e-5f);
    }
}

// ---------------------------------------------------------------------------
__global__ void split_w(const float* __restrict__ Wq, const float* __restrict__ Wk,
                        const float* __restrict__ Wp)
{
    int i = blockIdx.x*256 + threadIdx.x;
    if (i >= 3*CC*CC) return;
    int sel = i / (CC*CC);
    int r   = i - sel*(CC*CC);
    const float* src = (sel == 0) ? Wq : (sel == 1 ? Wk : Wp);
    float w = src[r];
    __half h = __float2half_rn(w);
    g_whi[i] = h;
    g_wlo[i] = __float2half_rn(w - __half2float(h));
}

// ---------------------------------------------------------------------------
// x[z][c][n] -> g_xt fp32 + g_xhi fp16, layout [z][n][c], rows >=196 zeroed.
__global__ void transpose_x(const float* __restrict__ x)
{
    __shared__ float S[32][33];
    const int z = blockIdx.x, ct = blockIdx.y, nt = blockIdx.z;
    const int tx = threadIdx.x, ty = threadIdx.y;
    #pragma unroll
    for (int u = 0; u < 4; u++) {
        int c = ct*32 + ty + u*8;
        int n = nt*32 + tx;
        if (n < NN) S[ty + u*8][tx] = x[((size_t)z*CC + c)*NN + n];
    }
    __syncthreads();
    const int c = ct*32 + tx;
    #pragma unroll
    for (int u = 0; u < 4; u++) {
        int n = nt*32 + ty + u*8;
        if (n >= NP) continue;
        float v = (n < NN) ? S[tx][ty + u*8] : 0.f;
        size_t o = ((size_t)z*NP + n)*CC + c;
        g_xt[o]  = v;
        g_xhi[o] = __float2half_rn(v);
    }
}

// ---------------------------------------------------------------------------
// g_yt[z][n][c] = (k_spike & attn) in {0,1} fp16 (exact), padded rows zeroed.
__global__ void build_yt()
{
    __shared__ unsigned char S[32][33];
    const int z = blockIdx.x, ct = blockIdx.y, nt = blockIdx.z;
    const int tx = threadIdx.x, ty = threadIdx.y;
    #pragma unroll
    for (int u = 0; u < 4; u++) {
        int c = ct*32 + ty + u*8;
        int n = nt*32 + tx;
        if (n < NN) S[ty + u*8][tx] = g_ks[((size_t)z*CC + c)*NN + n];
    }
    __syncthreads();
    const int c = ct*32 + tx;
    const int h = c / DHD;
    #pragma unroll
    for (int u = 0; u < 4; u++) {
        int n = nt*32 + ty + u*8;
        if (n >= NP) continue;
        float v = 0.f;
        if (n < NN) {
            unsigned char a = g_attn[((size_t)z*NHEAD + h)*NN + n];
            v = (S[tx][ty + u*8] & a) ? 1.0f : 0.0f;
        }
        g_yt[((size_t)z*NP + n)*CC + c] = __float2half_rn(v);
    }
}

// ---------------------------------------------------------------------------
// fp16 2-term split GEMM for q & k. Grid (6, 2, 256): mt, n-half, z.
// CTA: 128M x 104N, 256 thr, 2 CTAs/SM. Warp = 1 m16 x 13 n8 (acc 52).
// BK=32 (2 k16), cp.async 3-stage pipeline.
__global__ __launch_bounds__(256, 2) void gemm_qk_mma(
    const float* __restrict__ qbeta, const float* __restrict__ qmean,
    const float* __restrict__ kbeta, const float* __restrict__ kmean)
{
    extern __shared__ char sm[];
    const int mt = blockIdx.x, nh = blockIdx.y, z = blockIdx.z;
    const int sel = (mt >= 3) ? 1 : 0;
    const int mbase = (mt - sel*3) * 128;
    const int tid = threadIdx.x, wid = tid >> 5, lid = tid & 31;
    const int r = lid >> 2, cq = lid & 3;
    const uint32_t sb = smem_u32(sm);

    const __half* __restrict__ whiP = g_whi + (size_t)sel*CC*CC + (size_t)mbase*CC;
    const __half* __restrict__ wloP = g_wlo + (size_t)sel*CC*CC + (size_t)mbase*CC;
    const __half* __restrict__ bP   = g_xhi + ((size_t)z*NP + nh*NH)*CC;

    float acc[52];
    #pragma unroll
    for (int i = 0; i < 52; i++) acc[i] = 0.f;

    auto load_stage = [&](int s) {
        int kof = s * 32;
        uint32_t sa = sb + (s % 3)*S_STG;
        #pragma unroll
        for (int u = 0; u < 4; u++) {            // A: 1024 cp16 (hi+lo)
            int idx = tid + u*256;
            int plane = idx >> 9;
            int row   = (idx >> 2) & 127;
            int c4    = idx & 3;
            const __half* g = (plane ? wloP : whiP) + (size_t)row*CC + kof + c4*8;
            cp16(sa + plane*S_ALO + row*80 + c4*16, g);
        }
        #pragma unroll
        for (int u = 0; u < 2; u++) {            // B: 416 cp16
            int idx = tid + u*256;
            if (idx < 416) {
                int row = idx >> 2, c4 = idx & 3;
                cp16(sa + S_B + row*80 + c4*16, bP + (size_t)row*CC + kof + c4*8);
            }
        }
    };

    load_stage(0); CP_COMMIT();
    load_stage(1); CP_COMMIT();

    for (int kt = 0; kt < 12; kt++) {
        if (kt < 11) { CP_WAIT(1); } else { CP_WAIT(0); }
        __syncthreads();
        if (kt + 2 < 12) { load_stage(kt + 2); CP_COMMIT(); }

        const uint32_t* st  = (const uint32_t*)(sm + (kt % 3)*S_STG);
        const uint32_t* Ahi = st;
        const uint32_t* Alo = st + S_ALO/4;
        const uint32_t* Bs  = st + S_B/4;

        #pragma unroll
        for (int ks = 0; ks < 2; ks++) {
            const int kp = ks*8;
            uint32_t ah[4], al[4];
            int base = (wid*16 + r)*20 + kp + cq;
            ah[0] = Ahi[base];     ah[1] = Ahi[base + 160];
            ah[2] = Ahi[base + 4]; ah[3] = Ahi[base + 164];
            al[0] = Alo[base];     al[1] = Alo[base + 160];
            al[2] = Alo[base + 4]; al[3] = Alo[base + 164];
            #pragma unroll
            for (int nt = 0; nt < 13; nt++) {
                int nbase = (nt*8 + r)*20 + kp + cq;
                uint32_t b0 = Bs[nbase], b1 = Bs[nbase + 4];
                float* d = acc + nt*4;
                mma_f16(d, ah, b0, b1);
                mma_f16(d, al, b0, b1);
            }
        }
        __syncthreads();
    }

    // BN epilogue -> g_pre
    const int ch0 = mbase + wid*16 + r, ch1 = ch0 + 8;
    const float sc0 = g_scale[sel*CC + ch0], sc1 = g_scale[sel*CC + ch1];
    const float mu0 = (sel ? kmean : qmean)[ch0], mu1 = (sel ? kmean : qmean)[ch1];
    const float be0 = (sel ? kbeta : qbeta)[ch0], be1 = (sel ? kbeta : qbeta)[ch1];
    float* __restrict__ o0 = g_pre + (size_t)sel*TBCN + (size_t)z*CN + (size_t)ch0*NN;
    float* __restrict__ o1 = g_pre + (size_t)sel*TBCN + (size_t)z*CN + (size_t)ch1*NN;
    #pragma unroll
    for (int nt = 0; nt < 13; nt++) {
        int n = nh*NH + nt*8 + 2*cq;
        if (n < NN) {
            const float* d = acc + nt*4;
            float2 v0, v1;
            v0.x = (d[0] - mu0)*sc0 + be0;
            v0.y = (d[1] - mu0)*sc0 + be0;
            v1.x = (d[2] - mu1)*sc1 + be1;
            v1.y = (d[3] - mu1)*sc1 + be1;
            *(float2*)(o0 + n) = v0;
            *(float2*)(o1 + n) = v1;
        }
    }
}

// ---------------------------------------------------------------------------
// Projection GEMM: A = Wp 2-term fp16 split, B = yt exact {0,1}. Grid (3,2,256).
__global__ __launch_bounds__(256, 2) void gemm_p_mma(
    const float* __restrict__ bp,
    const float* __restrict__ pbeta, const float* __restrict__ pmean)
{
    extern __shared__ char sm[];
    const int mt = blockIdx.x, nh = blockIdx.y, z = blockIdx.z;
    const int mbase = mt * 128;
    const int tid = threadIdx.x, wid = tid >> 5, lid = tid & 31;
    const int r = lid >> 2, cq = lid & 3;
    const uint32_t sb = smem_u32(sm);

    const __half* __restrict__ whiP = g_whi + (size_t)2*CC*CC + (size_t)mbase*CC;
    const __half* __restrict__ wloP = g_wlo + (size_t)2*CC*CC + (size_t)mbase*CC;
    const __half* __restrict__ bP   = g_yt + ((size_t)z*NP + nh*NH)*CC;

    float acc[52];
    #pragma unroll
    for (int i = 0; i < 52; i++) acc[i] = 0.f;

    auto load_stage = [&](int s) {
        int kof = s * 32;
        uint32_t sa = sb + (s % 3)*S_STG;
        #pragma unroll
        for (int u = 0; u < 4; u++) {
            int idx = tid + u*256;
            int plane = idx >> 9;
            int row   = (idx >> 2) & 127;
            int c4    = idx & 3;
            const __half* g = (plane ? wloP : whiP) + (size_t)row*CC + kof + c4*8;
            cp16(sa + plane*S_ALO + row*80 + c4*16, g);
        }
        #pragma unroll
        for (int u = 0; u < 2; u++) {
            int idx = tid + u*256;
            if (idx < 416) {
                int row = idx >> 2, c4 = idx & 3;
                cp16(sa + S_B + row*80 + c4*16, bP + (size_t)row*CC + kof + c4*8);
            }
        }
    };

    load_stage(0); CP_COMMIT();
    load_stage(1); CP_COMMIT();

    for (int kt = 0; kt < 12; kt++) {
        if (kt < 11) { CP_WAIT(1); } else { CP_WAIT(0); }
        __syncthreads();
        if (kt + 2 < 12) { load_stage(kt + 2); CP_COMMIT(); }

        const uint32_t* st  = (const uint32_t*)(sm + (kt % 3)*S_STG);
        const uint32_t* Ahi = st;
        const uint32_t* Alo = st + S_ALO/4;
        const uint32_t* Bs  = st + S_B/4;

        #pragma unroll
        for (int ks = 0; ks < 2; ks++) {
            const int kp = ks*8;
            uint32_t ah[4], al[4];
            int base = (wid*16 + r)*20 + kp + cq;
            ah[0] = Ahi[base];     ah[1] = Ahi[base + 160];
            ah[2] = Ahi[base + 4]; ah[3] = Ahi[base + 164];
            al[0] = Alo[base];     al[1] = Alo[base + 160];
            al[2] = Alo[base + 4]; al[3] = Alo[base + 164];
            #pragma unroll
            for (int nt = 0; nt < 13; nt++) {
                int nbase = (nt*8 + r)*20 + kp + cq;
                uint32_t b0 = Bs[nbase], b1 = Bs[nbase + 4];
                float* d = acc + nt*4;
                mma_f16(d, ah, b0, b1);
                mma_f16(d, al, b0, b1);
            }
        }
        __syncthreads();
    }

    const int ch0 = mbase + wid*16 + r, ch1 = ch0 + 8;
    const float sc0 = g_scale[2*CC + ch0], sc1 = g_scale[2*CC + ch1];
    const float mu0 = pmean[ch0], mu1 = pmean[ch1];
    const float be0 = pbeta[ch0], be1 = pbeta[ch1];
    const float bv0 = bp[ch0],    bv1 = bp[ch1];
    float* __restrict__ o0 = g_pre + (size_t)z*CN + (size_t)ch0*NN;
    float* __restrict__ o1 = g_pre + (size_t)z*CN + (size_t)ch1*NN;
    #pragma unroll
    for (int nt = 0; nt < 13; nt++) {
        int n = nh*NH + nt*8 + 2*cq;
        if (n < NN) {
            const float* d = acc + nt*4;
            float2 v0, v1;
            v0.x = ((d[0] + bv0) - mu0)*sc0 + be0;
            v0.y = ((d[1] + bv0) - mu0)*sc0 + be0;
            v1.x = ((d[2] + bv1) - mu1)*sc1 + be1;
            v1.y = ((d[3] + bv1) - mu1)*sc1 + be1;
            *(float2*)(o0 + n) = v0;
            *(float2*)(o1 + n) = v1;
        }
    }
}

// ---------------------------------------------------------------------------
// LIF for q,k; near-threshold chains pushed to repair queue.
__global__ void lif_qk()
{
    int i = blockIdx.x*blockDim.x + threadIdx.x;
    if (i >= BCN) return;

    #pragma unroll
    for (int qk = 0; qk < 2; qk++) {
        const size_t base = (size_t)qk * TBCN;
        float v = 0.f, mn = 1e9f;
        unsigned char* __restrict__ sp = qk ? g_ks : g_qs;
        #pragma unroll
        for (int t = 0; t < TT; t++) {
            float xv = g_pre[base + (size_t)t*BCN + i];
            v += (xv - v)*0.5f;
            float d = fabsf(v - 1.f);
            if (d < mn) mn = d;
            unsigned char s = (v >= 1.f) ? 1 : 0;
            sp[(size_t)t*BCN + i] = s;
            if (s) v = 0.f;
        }
        if (mn < REPAIR_QK) {
            unsigned p = atomicAdd(&g_nfix, 1u);
            if (p < FIXCAP) g_fix[p] = i | (qk << 31);
        }
    }
}

// ---------------------------------------------------------------------------
// Warp-per-chain exact fp32 repair for q/k (coalesced g_xt reads).
__global__ void repair_qk(const float* __restrict__ Wq, const float* __restrict__ Wk,
                          const float* __restrict__ qbeta, const float* __restrict__ qmean,
                          const float* __restrict__ kbeta, const float* __restrict__ kmean)
{
    unsigned total = g_nfix;
    if (total > FIXCAP) total = FIXCAP;
    const int nwarp = gridDim.x * (blockDim.x >> 5);
    const int w = (blockIdx.x*blockDim.x + threadIdx.x) >> 5;
    const int lane = threadIdx.x & 31;

    for (unsigned j = w; j < total; j += nwarp) {
        int e  = g_fix[j];
        int qk = (e >> 31) & 1;
        int i  = e & 0x7FFFFFFF;
        int b  = i / CN;
        int rr = i - b*CN;
        int ch = rr / NN;
        int n  = rr - ch*NN;

        const float* __restrict__ wr = (qk ? Wk : Wq) + (size_t)ch*CC;
        const float sc = g_scale[qk*CC + ch];
        const float mu = (qk ? kmean : qmean)[ch];
        const float be = (qk ? kbeta : qbeta)[ch];
        unsigned char* __restrict__ sp = qk ? g_ks : g_qs;

        float v = 0.f;
        for (int t = 0; t < TT; t++) {
            const float* __restrict__ xr =
                g_xt + ((size_t)(t*BB + b)*NP + n)*CC;
            float part = 0.f;
            #pragma unroll
            for (int c = 0; c < CC/32; c++)
                part = fmaf(wr[lane + 32*c], xr[lane + 32*c], part);
            #pragma unroll
            for (int o = 16; o; o >>= 1)
                part += __shfl_xor_sync(0xFFFFFFFFu, part, o);
            float pre = (part - mu)*sc + be;
            v += (pre - v)*0.5f;
            unsigned char s = (v >= 1.f) ? 1 : 0;
            if (lane == 0) sp[(size_t)t*BCN + i] = s;
            if (s) v = 0.f;
        }
    }
}

// ---------------------------------------------------------------------------
__global__ void attn_kernel()
{
    int idx = blockIdx.x*blockDim.x + threadIdx.x;
    if (idx >= BHN) return;
    int n = idx % NN;
    int h = (idx / NN) % NHEAD;
    int b = idx / (NN*NHEAD);

    float v = 0.f;
    #pragma unroll
    for (int t = 0; t < TT; t++) {
        const unsigned char* __restrict__ p =
            g_qs + ((size_t)(t*BB + b)*CC + h*DHD)*NN + n;
        int s = 0;
        #pragma unroll
        for (int i2 = 0; i2 < DHD; i2++) s += p[(size_t)i2*NN];
        float sf = (float)s;
        v = v + (sf - v)*0.5f;
        unsigned char a = (v >= 1.0f) ? 1 : 0;
        g_attn[((size_t)(t*BB + b)*NHEAD + h)*NN + n] = a;
        if (a) v = 0.f;
    }
}

// ---------------------------------------------------------------------------
// Final LIF; flags near-threshold chains for warp repair.
__global__ void lif_out(float* __restrict__ out)
{
    int i = blockIdx.x*blockDim.x + threadIdx.x;
    if (i >= BCN) return;

    float v = 0.f, mn = 1e9f;
    #pragma unroll
    for (int t = 0; t < TT; t++) {
        float xv = g_pre[(size_t)t*BCN + i];
        v += (xv - v)*0.5f;
        float d = fabsf(v - 1.f);
        if (d < mn) mn = d;
        float s = (v >= 1.f) ? 1.f : 0.f;
        out[(size_t)t*BCN + i] = s;
        if (s != 0.f) v = 0.f;
    }
    if (mn < REPAIR_OUT) {
        unsigned p = atomicAdd(&g_nfix2, 1u);
        if (p < FIXCAP) g_fix2[p] = i;
    }
}

// ---------------------------------------------------------------------------
// Warp-per-chain exact fp32 repair for the output LIF (reads g_yt, coalesced).
__global__ void repair_out(float* __restrict__ out,
                           const float* __restrict__ Wp, const float* __restrict__ bp,
                           const float* __restrict__ pbeta, const float* __restrict__ pmean)
{
    unsigned total = g_nfix2;
    if (total > FIXCAP) total = FIXCAP;
    const int nwarp = gridDim.x * (blockDim.x >> 5);
    const int w = (blockIdx.x*blockDim.x + threadIdx.x) >> 5;
    const int lane = threadIdx.x & 31;

    for (unsigned j = w; j < total; j += nwarp) {
        int i  = g_fix2[j];
        int b  = i / CN;
        int rr = i - b*CN;
        int ch = rr / NN;
        int n  = rr - ch*NN;

        const float* __restrict__ wr = Wp + (size_t)ch*CC;
        const float sc = g_scale[2*CC + ch];
        const float mu = pmean[ch], be = pbeta[ch], bv = bp[ch];

        float v = 0.f;
        for (int t = 0; t < TT; t++) {
            const __half* __restrict__ yr =
                g_yt + ((size_t)(t*BB + b)*NP + n)*CC;
            float part = 0.f;
            #pragma unroll
            for (int c = 0; c < CC/32; c++)
                part = fmaf(wr[lane + 32*c],
                            __half2float(yr[lane + 32*c]), part);
            #pragma unroll
            for (int o = 16; o; o >>= 1)
                part += __shfl_xor_sync(0xFFFFFFFFu, part, o);
            float pre = ((part + bv) - mu)*sc + be;
            v += (pre - v)*0.5f;
            float s = (v >= 1.f) ? 1.f : 0.f;
            if (lane == 0) out[(size_t)t*BCN + i] = s;
            if (s != 0.f) v = 0.f;
        }
    }
}

// ---------------------------------------------------------------------------
extern "C" void kernel_launch(void* const* d_in, const int* in_sizes, int n_in,
                              void* d_out, int out_size)
{
    const float* x   = (const float*)d_in[0];
    const float* Wq  = (const float*)d_in[1];
    const float* qg  = (const float*)d_in[2];
    const float* qb  = (const float*)d_in[3];
    const float* qm  = (const float*)d_in[4];
    const float* qv  = (const float*)d_in[5];
    const float* Wk  = (const float*)d_in[6];
    const float* kg  = (const float*)d_in[7];
    const float* kb  = (const float*)d_in[8];
    const float* km  = (const float*)d_in[9];
    const float* kv  = (const float*)d_in[10];
    const float* Wp  = (const float*)d_in[11];
    const float* bp  = (const float*)d_in[12];
    const float* pg  = (const float*)d_in[13];
    const float* pb  = (const float*)d_in[14];
    const float* pm  = (const float*)d_in[15];
    const float* pv  = (const float*)d_in[16];
    float* out = (float*)d_out;

    cudaFuncSetAttribute(gemm_qk_mma, cudaFuncAttributeMaxDynamicSharedMemorySize, SMEM_G);
    cudaFuncSetAttribute(gemm_p_mma,  cudaFuncAttributeMaxDynamicSharedMemorySize, SMEM_G);

    reset_counters<<<1, 32>>>();
    bn_precompute<<<1, CC>>>(qg, qv, kg, kv, pg, pv);
    split_w<<<(3*CC*CC + 255)/256, 256>>>(Wq, Wk, Wp);
    transpose_x<<<dim3(ZTOT, 12, 7), dim3(32, 8)>>>(x);
    gemm_qk_mma<<<dim3(6, 2, ZTOT), 256, SMEM_G>>>(qb, qm, kb, km);
    lif_qk<<<(BCN + 255)/256, 256>>>();
    repair_qk<<<256, 256>>>(Wq, Wk, qb, qm, kb, km);
    attn_kernel<<<(BHN + 255)/256, 256>>>();
    build_yt<<<dim3(ZTOT, 12, 7), dim3(32, 8)>>>();
    gemm_p_mma<<<dim3(3, 2, ZTOT), 256, SMEM_G>>>(bp, pb, pm);
    lif_out<<<(BCN + 255)/256, 256>>>(out);
    repair_out<<<256, 256>>>(out, Wp, bp, pb, pm);
}

// round 15
// speedup vs baseline: 1.0325x; 1.0325x over previous
#include <cuda_runtime.h>
#include <cuda_fp16.h>
#include <cstdint>
#include <math.h>

// Problem constants
#define TT    4
#define BB    64
#define CC    384
#define NN    196
#define NP    208             // padded N (mult of 16; rows 196..207 zeroed)
#define NH    104             // N half per CTA
#define NHEAD 8
#define DHD   48
#define CN    (CC*NN)          // 75264
#define BCN   (BB*CC*NN)       // 4816896
#define TBCN  (TT*BCN)         // 19267584
#define BHN   (BB*NHEAD*NN)    // 100352
#define ZTOT  (TT*BB)          // 256

// GEMM SMEM: stage = Ahi(128x40h) Alo(128x40h) B(104x40h); 3 stages; 2 CTA/SM.
#define S_ALO   10240
#define S_B     20480
#define S_STG   28800
#define SMEM_G  (3*S_STG)      // 86400 (x2 CTAs = 172.8KB <= 228KB)

#define REPAIR_QK  8e-3f
#define REPAIR_OUT 2.5e-4f
#define FIXCAP     (1<<21)

// Scratch (allocation-free: __device__ globals)
__device__ __half  g_preh[2u*TBCN];             // fp16 q/k pre-activations
__device__ float   g_pre[TBCN];                 // fp32 projection pre
__device__ float   g_xt [(size_t)ZTOT*NP*CC];   // fp32 x, [z][n][c] (repair)
__device__ __half  g_xhi[(size_t)ZTOT*NP*CC];   // fp16(x), [z][n][c]
__device__ __half  g_yt [(size_t)ZTOT*NP*CC];   // {0,1}
__device__ __half  g_whi[3*CC*CC];              // [sel][m][k] sel:0=q,1=k,2=p
__device__ __half  g_wlo[3*CC*CC];
__device__ unsigned char g_qs[TBCN];
__device__ unsigned char g_ks[TBCN];
__device__ unsigned char g_attn[(size_t)TT*BHN];
__device__ float   g_scale[3*CC];
__device__ unsigned int g_nfix;
__device__ unsigned int g_nfix2;
__device__ int     g_fix [FIXCAP];
__device__ int     g_fix2[FIXCAP];

// ---------------------------------------------------------------------------
__device__ __forceinline__ uint32_t smem_u32(const void* p) {
    uint32_t a;
    asm("{ .reg .u64 t; cvta.to.shared.u64 t, %1; cvt.u32.u64 %0, t; }"
        : "=r"(a) : "l"(p));
    return a;
}
__device__ __forceinline__ void cp16(uint32_t s, const void* g) {
    asm volatile("cp.async.cg.shared.global [%0], [%1], 16;"
                 :: "r"(s), "l"(g) : "memory");
}
#define CP_COMMIT() asm volatile("cp.async.commit_group;" ::: "memory")
#define CP_WAIT(n)  asm volatile("cp.async.wait_group %0;" :: "n"(n) : "memory")

__device__ __forceinline__ void mma_f16(float* d, const uint32_t* a,
                                        uint32_t b0, uint32_t b1) {
    asm volatile(
        "mma.sync.aligned.m16n8k16.row.col.f32.f16.f16.f32 "
        "{%0,%1,%2,%3}, {%4,%5,%6,%7}, {%8,%9}, {%0,%1,%2,%3};"
        : "+f"(d[0]), "+f"(d[1]), "+f"(d[2]), "+f"(d[3])
        : "r"(a[0]), "r"(a[1]), "r"(a[2]), "r"(a[3]), "r"(b0), "r"(b1));
}

// ---------------------------------------------------------------------------
__global__ void reset_counters()
{
    if (threadIdx.x == 0) { g_nfix = 0; g_nfix2 = 0; }
}

// ---------------------------------------------------------------------------
__global__ void bn_precompute(const float* __restrict__ qg, const float* __restrict__ qv,
                              const float* __restrict__ kg, const float* __restrict__ kv,
                              const float* __restrict__ pg, const float* __restrict__ pv)
{
    int c = threadIdx.x;
    if (c < CC) {
        g_scale[c]        = qg[c] / sqrtf(qv[c] + 1e-5f);
        g_scale[CC + c]   = kg[c] / sqrtf(kv[c] + 1e-5f);
        g_scale[2*CC + c] = pg[c] / sqrtf(pv[c] + 1e-5f);
    }
}

// ---------------------------------------------------------------------------
__global__ void split_w(const float* __restrict__ Wq, const float* __restrict__ Wk,
                        const float* __restrict__ Wp)
{
    int i = blockIdx.x*256 + threadIdx.x;
    if (i >= 3*CC*CC) return;
    int sel = i / (CC*CC);
    int r   = i - sel*(CC*CC);
    const float* src = (sel == 0) ? Wq : (sel == 1 ? Wk : Wp);
    float w = src[r];
    __half h = __float2half_rn(w);
    g_whi[i] = h;
    g_wlo[i] = __float2half_rn(w - __half2float(h));
}

// ---------------------------------------------------------------------------
// x[z][c][n] -> g_xt fp32 + g_xhi fp16, layout [z][n][c], rows >=196 zeroed.
__global__ void transpose_x(const float* __restrict__ x)
{
    __shared__ float S[32][33];
    const int z = blockIdx.x, ct = blockIdx.y, nt = blockIdx.z;
    const int tx = threadIdx.x, ty = threadIdx.y;
    #pragma unroll
    for (int u = 0; u < 4; u++) {
        int c = ct*32 + ty + u*8;
        int n = nt*32 + tx;
        if (n < NN) S[ty + u*8][tx] = x[((size_t)z*CC + c)*NN + n];
    }
    __syncthreads();
    const int c = ct*32 + tx;
    #pragma unroll
    for (int u = 0; u < 4; u++) {
        int n = nt*32 + ty + u*8;
        if (n >= NP) continue;
        float v = (n < NN) ? S[tx][ty + u*8] : 0.f;
        size_t o = ((size_t)z*NP + n)*CC + c;
        g_xt[o]  = v;
        g_xhi[o] = __float2half_rn(v);
    }
}

// ---------------------------------------------------------------------------
// g_yt[z][n][c] = (k_spike & attn) in {0,1} fp16 (exact), padded rows zeroed.
__global__ void build_yt()
{
    __shared__ unsigned char S[32][33];
    const int z = blockIdx.x, ct = blockIdx.y, nt = blockIdx.z;
    const int tx = threadIdx.x, ty = threadIdx.y;
    #pragma unroll
    for (int u = 0; u < 4; u++) {
        int c = ct*32 + ty + u*8;
        int n = nt*32 + tx;
        if (n < NN) S[ty + u*8][tx] = g_ks[((size_t)z*CC + c)*NN + n];
    }
    __syncthreads();
    const int c = ct*32 + tx;
    const int h = c / DHD;
    #pragma unroll
    for (int u = 0; u < 4; u++) {
        int n = nt*32 + ty + u*8;
        if (n >= NP) continue;
        float v = 0.f;
        if (n < NN) {
            unsigned char a = g_attn[((size_t)z*NHEAD + h)*NN + n];
            v = (S[tx][ty + u*8] & a) ? 1.0f : 0.0f;
        }
        g_yt[((size_t)z*NP + n)*CC + c] = __float2half_rn(v);
    }
}

// ---------------------------------------------------------------------------
// fp16 2-term split GEMM for q & k. Grid (6, 2, 256): mt, n-half, z.
// CTA: 128M x 104N, 256 thr, 2 CTAs/SM. Warp = 1 m16 x 13 n8 (acc 52).
// BK=32 (2 k16), cp.async 3-stage pipeline. Epilogue: BN -> fp16 g_preh.
__global__ __launch_bounds__(256, 2) void gemm_qk_mma(
    const float* __restrict__ qbeta, const float* __restrict__ qmean,
    const float* __restrict__ kbeta, const float* __restrict__ kmean)
{
    extern __shared__ char sm[];
    const int mt = blockIdx.x, nh = blockIdx.y, z = blockIdx.z;
    const int sel = (mt >= 3) ? 1 : 0;
    const int mbase = (mt - sel*3) * 128;
    const int tid = threadIdx.x, wid = tid >> 5, lid = tid & 31;
    const int r = lid >> 2, cq = lid & 3;
    const uint32_t sb = smem_u32(sm);

    const __half* __restrict__ whiP = g_whi + (size_t)sel*CC*CC + (size_t)mbase*CC;
    const __half* __restrict__ wloP = g_wlo + (size_t)sel*CC*CC + (size_t)mbase*CC;
    const __half* __restrict__ bP   = g_xhi + ((size_t)z*NP + nh*NH)*CC;

    float acc[52];
    #pragma unroll
    for (int i = 0; i < 52; i++) acc[i] = 0.f;

    auto load_stage = [&](int s) {
        int kof = s * 32;
        uint32_t sa = sb + (s % 3)*S_STG;
        #pragma unroll
        for (int u = 0; u < 4; u++) {            // A: 1024 cp16 (hi+lo)
            int idx = tid + u*256;
            int plane = idx >> 9;
            int row   = (idx >> 2) & 127;
            int c4    = idx & 3;
            const __half* g = (plane ? wloP : whiP) + (size_t)row*CC + kof + c4*8;
            cp16(sa + plane*S_ALO + row*80 + c4*16, g);
        }
        #pragma unroll
        for (int u = 0; u < 2; u++) {            // B: 416 cp16
            int idx = tid + u*256;
            if (idx < 416) {
                int row = idx >> 2, c4 = idx & 3;
                cp16(sa + S_B + row*80 + c4*16, bP + (size_t)row*CC + kof + c4*8);
            }
        }
    };

    load_stage(0); CP_COMMIT();
    load_stage(1); CP_COMMIT();

    for (int kt = 0; kt < 12; kt++) {
        if (kt < 11) { CP_WAIT(1); } else { CP_WAIT(0); }
        __syncthreads();
        if (kt + 2 < 12) { load_stage(kt + 2); CP_COMMIT(); }

        const uint32_t* st  = (const uint32_t*)(sm + (kt % 3)*S_STG);
        const uint32_t* Ahi = st;
        const uint32_t* Alo = st + S_ALO/4;
        const uint32_t* Bs  = st + S_B/4;

        #pragma unroll
        for (int ks = 0; ks < 2; ks++) {
            const int kp = ks*8;
            uint32_t ah[4], al[4];
            int base = (wid*16 + r)*20 + kp + cq;
            ah[0] = Ahi[base];     ah[1] = Ahi[base + 160];
            ah[2] = Ahi[base + 4]; ah[3] = Ahi[base + 164];
            al[0] = Alo[base];     al[1] = Alo[base + 160];
            al[2] = Alo[base + 4]; al[3] = Alo[base + 164];
            #pragma unroll
            for (int nt = 0; nt < 13; nt++) {
                int nbase = (nt*8 + r)*20 + kp + cq;
                uint32_t b0 = Bs[nbase], b1 = Bs[nbase + 4];
                float* d = acc + nt*4;
                mma_f16(d, ah, b0, b1);
                mma_f16(d, al, b0, b1);
            }
        }
        __syncthreads();
    }

    // BN epilogue -> fp16 g_preh
    const int ch0 = mbase + wid*16 + r, ch1 = ch0 + 8;
    const float sc0 = g_scale[sel*CC + ch0], sc1 = g_scale[sel*CC + ch1];
    const float mu0 = (sel ? kmean : qmean)[ch0], mu1 = (sel ? kmean : qmean)[ch1];
    const float be0 = (sel ? kbeta : qbeta)[ch0], be1 = (sel ? kbeta : qbeta)[ch1];
    __half* __restrict__ o0 = g_preh + (size_t)sel*TBCN + (size_t)z*CN + (size_t)ch0*NN;
    __half* __restrict__ o1 = g_preh + (size_t)sel*TBCN + (size_t)z*CN + (size_t)ch1*NN;
    #pragma unroll
    for (int nt = 0; nt < 13; nt++) {
        int n = nh*NH + nt*8 + 2*cq;
        if (n < NN) {
            const float* d = acc + nt*4;
            *(__half2*)(o0 + n) = __floats2half2_rn((d[0] - mu0)*sc0 + be0,
                                                    (d[1] - mu0)*sc0 + be0);
            *(__half2*)(o1 + n) = __floats2half2_rn((d[2] - mu1)*sc1 + be1,
                                                    (d[3] - mu1)*sc1 + be1);
        }
    }
}

// ---------------------------------------------------------------------------
// Projection GEMM: A = Wp 2-term fp16 split, B = yt exact {0,1}. Grid (3,2,256).
// Epilogue: bias + BN -> fp32 g_pre.
__global__ __launch_bounds__(256, 2) void gemm_p_mma(
    const float* __restrict__ bp,
    const float* __restrict__ pbeta, const float* __restrict__ pmean)
{
    extern __shared__ char sm[];
    const int mt = blockIdx.x, nh = blockIdx.y, z = blockIdx.z;
    const int mbase = mt * 128;
    const int tid = threadIdx.x, wid = tid >> 5, lid = tid & 31;
    const int r = lid >> 2, cq = lid & 3;
    const uint32_t sb = smem_u32(sm);

    const __half* __restrict__ whiP = g_whi + (size_t)2*CC*CC + (size_t)mbase*CC;
    const __half* __restrict__ wloP = g_wlo + (size_t)2*CC*CC + (size_t)mbase*CC;
    const __half* __restrict__ bP   = g_yt + ((size_t)z*NP + nh*NH)*CC;

    float acc[52];
    #pragma unroll
    for (int i = 0; i < 52; i++) acc[i] = 0.f;

    auto load_stage = [&](int s) {
        int kof = s * 32;
        uint32_t sa = sb + (s % 3)*S_STG;
        #pragma unroll
        for (int u = 0; u < 4; u++) {
            int idx = tid + u*256;
            int plane = idx >> 9;
            int row   = (idx >> 2) & 127;
            int c4    = idx & 3;
            const __half* g = (plane ? wloP : whiP) + (size_t)row*CC + kof + c4*8;
            cp16(sa + plane*S_ALO + row*80 + c4*16, g);
        }
        #pragma unroll
        for (int u = 0; u < 2; u++) {
            int idx = tid + u*256;
            if (idx < 416) {
                int row = idx >> 2, c4 = idx & 3;
                cp16(sa + S_B + row*80 + c4*16, bP + (size_t)row*CC + kof + c4*8);
            }
        }
    };

    load_stage(0); CP_COMMIT();
    load_stage(1); CP_COMMIT();

    for (int kt = 0; kt < 12; kt++) {
        if (kt < 11) { CP_WAIT(1); } else { CP_WAIT(0); }
        __syncthreads();
        if (kt + 2 < 12) { load_stage(kt + 2); CP_COMMIT(); }

        const uint32_t* st  = (const uint32_t*)(sm + (kt % 3)*S_STG);
        const uint32_t* Ahi = st;
        const uint32_t* Alo = st + S_ALO/4;
        const uint32_t* Bs  = st + S_B/4;

        #pragma unroll
        for (int ks = 0; ks < 2; ks++) {
            const int kp = ks*8;
            uint32_t ah[4], al[4];
            int base = (wid*16 + r)*20 + kp + cq;
            ah[0] = Ahi[base];     ah[1] = Ahi[base + 160];
            ah[2] = Ahi[base + 4]; ah[3] = Ahi[base + 164];
            al[0] = Alo[base];     al[1] = Alo[base + 160];
            al[2] = Alo[base + 4]; al[3] = Alo[base + 164];
            #pragma unroll
            for (int nt = 0; nt < 13; nt++) {
                int nbase = (nt*8 + r)*20 + kp + cq;
                uint32_t b0 = Bs[nbase], b1 = Bs[nbase + 4];
                float* d = acc + nt*4;
                mma_f16(d, ah, b0, b1);
                mma_f16(d, al, b0, b1);
            }
        }
        __syncthreads();
    }

    const int ch0 = mbase + wid*16 + r, ch1 = ch0 + 8;
    const float sc0 = g_scale[2*CC + ch0], sc1 = g_scale[2*CC + ch1];
    const float mu0 = pmean[ch0], mu1 = pmean[ch1];
    const float be0 = pbeta[ch0], be1 = pbeta[ch1];
    const float bv0 = bp[ch0],    bv1 = bp[ch1];
    float* __restrict__ o0 = g_pre + (size_t)z*CN + (size_t)ch0*NN;
    float* __restrict__ o1 = g_pre + (size_t)z*CN + (size_t)ch1*NN;
    #pragma unroll
    for (int nt = 0; nt < 13; nt++) {
        int n = nh*NH + nt*8 + 2*cq;
        if (n < NN) {
            const float* d = acc + nt*4;
            float2 v0, v1;
            v0.x = ((d[0] + bv0) - mu0)*sc0 + be0;
            v0.y = ((d[1] + bv0) - mu0)*sc0 + be0;
            v1.x = ((d[2] + bv1) - mu1)*sc1 + be1;
            v1.y = ((d[3] + bv1) - mu1)*sc1 + be1;
            *(float2*)(o0 + n) = v0;
            *(float2*)(o1 + n) = v1;
        }
    }
}

// ---------------------------------------------------------------------------
// LIF for q,k (fp16 pre, 4 elems/thread); near-threshold -> repair queue.
__global__ void lif_qk()
{
    int i4 = blockIdx.x*blockDim.x + threadIdx.x;
    if (i4 >= BCN/4) return;
    const size_t i = (size_t)i4 * 4;

    #pragma unroll
    for (int qk = 0; qk < 2; qk++) {
        const size_t base = (size_t)qk * TBCN;
        unsigned char* __restrict__ sp = qk ? g_ks : g_qs;
        float v[4]  = {0.f, 0.f, 0.f, 0.f};
        float mn[4] = {1e9f, 1e9f, 1e9f, 1e9f};
        #pragma unroll
        for (int t = 0; t < TT; t++) {
            uint2 pk = *(const uint2*)(g_preh + base + (size_t)t*BCN + i);
            __half2 h0 = *(__half2*)&pk.x;
            __half2 h1 = *(__half2*)&pk.y;
            float xs[4] = { __low2float(h0), __high2float(h0),
                            __low2float(h1), __high2float(h1) };
            uchar4 s4;
            unsigned char* sb = (unsigned char*)&s4;
            #pragma unroll
            for (int j = 0; j < 4; j++) {
                v[j] += (xs[j] - v[j])*0.5f;
                float d = fabsf(v[j] - 1.f);
                if (d < mn[j]) mn[j] = d;
                unsigned char s = (v[j] >= 1.f) ? 1 : 0;
                sb[j] = s;
                if (s) v[j] = 0.f;
            }
            *(uchar4*)(sp + (size_t)t*BCN + i) = s4;
        }
        #pragma unroll
        for (int j = 0; j < 4; j++) {
            if (mn[j] < REPAIR_QK) {
                unsigned p = atomicAdd(&g_nfix, 1u);
                if (p < FIXCAP) g_fix[p] = (int)(i + j) | (qk << 31);
            }
        }
    }
}

// ---------------------------------------------------------------------------
// Warp-per-chain exact fp32 repair for q/k (coalesced g_xt reads).
__global__ void repair_qk(const float* __restrict__ Wq, const float* __restrict__ Wk,
                          const float* __restrict__ qbeta, const float* __restrict__ qmean,
                          const float* __restrict__ kbeta, const float* __restrict__ kmean)
{
    unsigned total = g_nfix;
    if (total > FIXCAP) total = FIXCAP;
    const int nwarp = gridDim.x * (blockDim.x >> 5);
    const int w = (blockIdx.x*blockDim.x + threadIdx.x) >> 5;
    const int lane = threadIdx.x & 31;

    for (unsigned j = w; j < total; j += nwarp) {
        int e  = g_fix[j];
        int qk = (e >> 31) & 1;
        int i  = e & 0x7FFFFFFF;
        int b  = i / CN;
        int rr = i - b*CN;
        int ch = rr / NN;
        int n  = rr - ch*NN;

        const float* __restrict__ wr = (qk ? Wk : Wq) + (size_t)ch*CC;
        const float sc = g_scale[qk*CC + ch];
        const float mu = (qk ? kmean : qmean)[ch];
        const float be = (qk ? kbeta : qbeta)[ch];
        unsigned char* __restrict__ sp = qk ? g_ks : g_qs;

        float v = 0.f;
        for (int t = 0; t < TT; t++) {
            const float* __restrict__ xr =
                g_xt + ((size_t)(t*BB + b)*NP + n)*CC;
            float part = 0.f;
            #pragma unroll
            for (int c = 0; c < CC/32; c++)
                part = fmaf(wr[lane + 32*c], xr[lane + 32*c], part);
            #pragma unroll
            for (int o = 16; o; o >>= 1)
                part += __shfl_xor_sync(0xFFFFFFFFu, part, o);
            float pre = (part - mu)*sc + be;
            v += (pre - v)*0.5f;
            unsigned char s = (v >= 1.f) ? 1 : 0;
            if (lane == 0) sp[(size_t)t*BCN + i] = s;
            if (s) v = 0.f;
        }
    }
}

// ---------------------------------------------------------------------------
__global__ void attn_kernel()
{
    int idx = blockIdx.x*blockDim.x + threadIdx.x;
    if (idx >= BHN) return;
    int n = idx % NN;
    int h = (idx / NN) % NHEAD;
    int b = idx / (NN*NHEAD);

    float v = 0.f;
    #pragma unroll
    for (int t = 0; t < TT; t++) {
        const unsigned char* __restrict__ p =
            g_qs + ((size_t)(t*BB + b)*CC + h*DHD)*NN + n;
        int s = 0;
        #pragma unroll
        for (int i2 = 0; i2 < DHD; i2++) s += p[(size_t)i2*NN];
        float sf = (float)s;
        v = v + (sf - v)*0.5f;
        unsigned char a = (v >= 1.0f) ? 1 : 0;
        g_attn[((size_t)(t*BB + b)*NHEAD + h)*NN + n] = a;
        if (a) v = 0.f;
    }
}

// ---------------------------------------------------------------------------
// Final LIF (fp32 pre, 4 elems/thread); flags near-threshold chains.
__global__ void lif_out(float* __restrict__ out)
{
    int i4 = blockIdx.x*blockDim.x + threadIdx.x;
    if (i4 >= BCN/4) return;
    const size_t i = (size_t)i4 * 4;

    float v[4]  = {0.f, 0.f, 0.f, 0.f};
    float mn[4] = {1e9f, 1e9f, 1e9f, 1e9f};
    #pragma unroll
    for (int t = 0; t < TT; t++) {
        float4 xp = *(const float4*)(g_pre + (size_t)t*BCN + i);
        float xs[4] = { xp.x, xp.y, xp.z, xp.w };
        float4 s4;
        float* sb = (float*)&s4;
        #pragma unroll
        for (int j = 0; j < 4; j++) {
            v[j] += (xs[j] - v[j])*0.5f;
            float d = fabsf(v[j] - 1.f);
            if (d < mn[j]) mn[j] = d;
            float s = (v[j] >= 1.f) ? 1.f : 0.f;
            sb[j] = s;
            if (s != 0.f) v[j] = 0.f;
        }
        *(float4*)(out + (size_t)t*BCN + i) = s4;
    }
    #pragma unroll
    for (int j = 0; j < 4; j++) {
        if (mn[j] < REPAIR_OUT) {
            unsigned p = atomicAdd(&g_nfix2, 1u);
            if (p < FIXCAP) g_fix2[p] = (int)(i + j);
        }
    }
}

// ---------------------------------------------------------------------------
// Warp-per-chain exact fp32 repair for the output LIF (reads g_yt, coalesced).
__global__ void repair_out(float* __restrict__ out,
                           const float* __restrict__ Wp, const float* __restrict__ bp,
                           const float* __restrict__ pbeta, const float* __restrict__ pmean)
{
    unsigned total = g_nfix2;
    if (total > FIXCAP) total = FIXCAP;
    const int nwarp = gridDim.x * (blockDim.x >> 5);
    const int w = (blockIdx.x*blockDim.x + threadIdx.x) >> 5;
    const int lane = threadIdx.x & 31;

    for (unsigned j = w; j < total; j += nwarp) {
        int i  = g_fix2[j];
        int b  = i / CN;
        int rr = i - b*CN;
        int ch = rr / NN;
        int n  = rr - ch*NN;

        const float* __restrict__ wr = Wp + (size_t)ch*CC;
        const float sc = g_scale[2*CC + ch];
        const float mu = pmean[ch], be = pbeta[ch], bv = bp[ch];

        float v = 0.f;
        for (int t = 0; t < TT; t++) {
            const __half* __restrict__ yr =
                g_yt + ((size_t)(t*BB + b)*NP + n)*CC;
            float part = 0.f;
            #pragma unroll
            for (int c = 0; c < CC/32; c++)
                part = fmaf(wr[lane + 32*c],
                            __half2float(yr[lane + 32*c]), part);
            #pragma unroll
            for (int o = 16; o; o >>= 1)
                part += __shfl_xor_sync(0xFFFFFFFFu, part, o);
            float pre = ((part + bv) - mu)*sc + be;
            v += (pre - v)*0.5f;
            float s = (v >= 1.f) ? 1.f : 0.f;
            if (lane == 0) out[(size_t)t*BCN + i] = s;
            if (s != 0.f) v = 0.f;
        }
    }
}

// ---------------------------------------------------------------------------
extern "C" void kernel_launch(void* const* d_in, const int* in_sizes, int n_in,
                              void* d_out, int out_size)
{
    const float* x   = (const float*)d_in[0];
    const float* Wq  = (const float*)d_in[1];
    const float* qg  = (const float*)d_in[2];
    const float* qb  = (const float*)d_in[3];
    const float* qm  = (const float*)d_in[4];
    const float* qv  = (const float*)d_in[5];
    const float* Wk  = (const float*)d_in[6];
    const float* kg  = (const float*)d_in[7];
    const float* kb  = (const float*)d_in[8];
    const float* km  = (const float*)d_in[9];
    const float* kv  = (const float*)d_in[10];
    const float* Wp  = (const float*)d_in[11];
    const float* bp  = (const float*)d_in[12];
    const float* pg  = (const float*)d_in[13];
    const float* pb  = (const float*)d_in[14];
    const float* pm  = (const float*)d_in[15];
    const float* pv  = (const float*)d_in[16];
    float* out = (float*)d_out;

    cudaFuncSetAttribute(gemm_qk_mma, cudaFuncAttributeMaxDynamicSharedMemorySize, SMEM_G);
    cudaFuncSetAttribute(gemm_p_mma,  cudaFuncAttributeMaxDynamicSharedMemorySize, SMEM_G);

    reset_counters<<<1, 32>>>();
    bn_precompute<<<1, CC>>>(qg, qv, kg, kv, pg, pv);
    split_w<<<(3*CC*CC + 255)/256, 256>>>(Wq, Wk, Wp);
    transpose_x<<<dim3(ZTOT, 12, 7), dim3(32, 8)>>>(x);
    gemm_qk_mma<<<dim3(6, 2, ZTOT), 256, SMEM_G>>>(qb, qm, kb, km);
    lif_qk<<<(BCN/4 + 255)/256, 256>>>();
    repair_qk<<<256, 256>>>(Wq, Wk, qb, qm, kb, km);
    attn_kernel<<<(BHN + 255)/256, 256>>>();
    build_yt<<<dim3(ZTOT, 12, 7), dim3(32, 8)>>>();
    gemm_p_mma<<<dim3(3, 2, ZTOT), 256, SMEM_G>>>(bp, pb, pm);
    lif_out<<<(BCN/4 + 255)/256, 256>>>(out);
    repair_out<<<256, 256>>>(out, Wp, bp, pb, pm);
}